// round 6
// baseline (speedup 1.0000x reference)
#include <cuda_runtime.h>
#include <cuda_bf16.h>
#include <cstdint>

// Batched greedy nearest-neighbor selection, 3-phase:
//   Phase 1: compress needed rows (unvisited + start) to uint16 keys (top 16
//            float bits, monotone for v>=0) into __device__ scratch. ~64MB hot,
//            L2-resident.
//   Phase 2: 1 warp/batch serial greedy over 2KB key rows from L2; exact
//            fp32 tie resolution only when the min key is duplicated (<1%).
// Output (float32): pred (B,N) then pred_len (B,).

#define BIGF 1.0e6f
#define MSK_CAP 4096
#define SCRATCH_ELEMS 64000000ull   // supports B*N*N <= 64M (B=64, N=1000)

__device__ unsigned short g_keys[SCRATCH_ELEMS];

__device__ __forceinline__ int decode_scalar(unsigned int w, int N)
{
    return (w <= (unsigned int)N) ? (int)w : (int)__uint_as_float(w);
}

__device__ __forceinline__ unsigned int detect_word_mode(const unsigned char* mraw)
{
    const unsigned int* mw = (const unsigned int*)mraw;
    bool all01 = true, allf = true;
    #pragma unroll 8
    for (int i = 0; i < 64; i++) {
        unsigned int w = mw[i];
        all01 &= (w == 0u || w == 1u);
        allf  &= (w == 0u || w == 0x3f800000u);
    }
    return (all01 || allf) ? 1u : 0u;
}

// ============================================================================
// Phase 1: one CTA per (b,row). Skip rows that are visited and not the start.
// ============================================================================
__global__ __launch_bounds__(128, 8)
void compress_kernel(const float* __restrict__ distance,
                     const unsigned char* __restrict__ mraw,
                     const unsigned int* __restrict__ start_raw,
                     int N)
{
    const int r   = blockIdx.x;          // 0 .. B*N-1
    const int b   = r / N;
    const int row = r % N;
    const int tid = threadIdx.x;

    __shared__ int s_need;
    if (tid == 0) {
        unsigned int wm = detect_word_mode(mraw);
        int start = decode_scalar(start_raw[b], N);
        bool visited;
        if (wm) visited = ((const unsigned int*)mraw)[(size_t)b * N + row] != 0u;
        else    visited = mraw[(size_t)b * N + row] != 0;
        s_need = (!visited || row == start) ? 1 : 0;
    }
    __syncthreads();
    if (!s_need) return;

    const float* src = distance + (size_t)r * N;
    unsigned short* dst = g_keys + (size_t)r * N;

    for (int c = tid * 4; c < N; c += 128 * 4) {
        if (c + 3 < N) {
            float4 v = *reinterpret_cast<const float4*>(src + c);
            ushort4 k;
            k.x = (unsigned short)(__float_as_uint(v.x) >> 16);
            k.y = (unsigned short)(__float_as_uint(v.y) >> 16);
            k.z = (unsigned short)(__float_as_uint(v.z) >> 16);
            k.w = (unsigned short)(__float_as_uint(v.w) >> 16);
            *reinterpret_cast<ushort4*>(dst + c) = k;
        } else {
            for (int j = c; j < N; j++)
                dst[j] = (unsigned short)(__float_as_uint(src[j]) >> 16);
        }
    }
}

// ============================================================================
// Phase 2: one warp per batch. Lane owns 32 cols: col = j*256 + lane*8 + p
// (j<4, p<8), i.e. key word t=j*4+w holds cols (j*256+lane*8+2w, +2w+1).
// pat[t] has 0xFFFF in each visited/OOB halfword; key|pat masks in one OR.
// ============================================================================
__global__ __launch_bounds__(32, 1)
void greedy_key_kernel(const float* __restrict__ distance,
                       const unsigned char* __restrict__ mraw,
                       const unsigned int* __restrict__ start_raw,
                       const unsigned int* __restrict__ pad_raw,
                       float* __restrict__ pred,
                       float* __restrict__ pred_len,
                       int N)
{
    const int lane = threadIdx.x;
    const int b    = blockIdx.x;
    const unsigned FULL = 0xffffffffu;

    const float* D = distance + (size_t)b * (size_t)N * (size_t)N;
    const unsigned short* KB = g_keys + (size_t)b * (size_t)N * (size_t)N;
    float* pred_b = pred + (size_t)b * N;

    unsigned int wm = 0; int point = 0, pad = N;
    if (lane == 0) {
        wm = detect_word_mode(mraw);
        point = decode_scalar(start_raw[b], N);
        if (pad_raw != nullptr) pad = decode_scalar(*pad_raw, N);
    }
    wm    = __shfl_sync(FULL, wm, 0);
    point = __shfl_sync(FULL, point, 0);
    pad   = __shfl_sync(FULL, pad, 0);

    // ---- init per-lane halfword mask patterns + count unvisited ----
    const unsigned int* m32 = (const unsigned int*)mraw + (size_t)b * N;
    const unsigned char* m8 = mraw + (size_t)b * N;
    unsigned int pat[16];
    int cnt = 0;
    #pragma unroll
    for (int t = 0; t < 16; t++) {
        unsigned int pw = 0;
        #pragma unroll
        for (int p = 0; p < 2; p++) {
            int col = (t >> 2) * 256 + lane * 8 + ((t & 3) << 1) + p;
            bool v;
            if (col < N) v = wm ? (m32[col] != 0u) : (m8[col] != 0);
            else         v = true;
            if (v) pw |= 0xFFFFu << (16 * p);
            else   cnt++;
        }
        pat[t] = pw;
    }
    int rem = (int)__reduce_add_sync(FULL, (unsigned)cnt);
    if (lane == 0) pred_len[b] = (float)rem;

    // ---- serial greedy loop ----
    int step = 0;
    while (rem > 0) {
        const unsigned short* __restrict__ krow = KB + (size_t)point * N;

        // load 16 key words (4 x LDG.128 for full chunks), apply mask
        unsigned int kw[16];
        #pragma unroll
        for (int j = 0; j < 4; j++) {
            int base = j * 256 + lane * 8;
            if (base + 8 <= N) {
                uint4 v = *reinterpret_cast<const uint4*>(krow + base);
                kw[j*4+0] = v.x | pat[j*4+0];
                kw[j*4+1] = v.y | pat[j*4+1];
                kw[j*4+2] = v.z | pat[j*4+2];
                kw[j*4+3] = v.w | pat[j*4+3];
            } else {
                #pragma unroll
                for (int w = 0; w < 4; w++) {
                    int c0 = base + 2 * w;
                    unsigned int v;
                    if (c0 + 2 <= N)      v = *reinterpret_cast<const unsigned int*>(krow + c0);
                    else if (c0 + 1 <= N) v = (unsigned int)krow[c0] | 0xFFFF0000u;
                    else                  v = 0xFFFFFFFFu;
                    kw[j*4+w] = v | pat[j*4+w];
                }
            }
        }

        // min over 32 u16 (lo/hi extract + tree)
        unsigned int mn = 0xFFFFu;
        #pragma unroll
        for (int t = 0; t < 16; t++) {
            unsigned int lo = kw[t] & 0xFFFFu;
            unsigned int hi = kw[t] >> 16;
            unsigned int m  = lo < hi ? lo : hi;
            mn = m < mn ? m : mn;
        }
        unsigned int gmin = __reduce_min_sync(FULL, mn);

        // find first matching column + count matches
        int local_col = 0x7fffffff;
        int mcnt = 0;
        #pragma unroll
        for (int t = 0; t < 16; t++) {
            int cbase = (t >> 2) * 256 + lane * 8 + ((t & 3) << 1);
            unsigned int lo = kw[t] & 0xFFFFu;
            unsigned int hi = kw[t] >> 16;
            if (lo == gmin) { local_col = local_col < cbase     ? local_col : cbase;     mcnt++; }
            if (hi == gmin) { local_col = local_col < cbase + 1 ? local_col : cbase + 1; mcnt++; }
        }
        int total = (int)__reduce_add_sync(FULL, (unsigned)mcnt);

        int idx;
        if (total == 1) {
            idx = (int)__reduce_min_sync(FULL, (unsigned)local_col);
        } else {
            // rare: duplicate min key -> exact fp32 resolution among matches
            const float* __restrict__ frow = D + (size_t)point * N;
            unsigned long long best = ~0ull;
            #pragma unroll
            for (int t = 0; t < 16; t++) {
                int cbase = (t >> 2) * 256 + lane * 8 + ((t & 3) << 1);
                unsigned int lo = kw[t] & 0xFFFFu;
                unsigned int hi = kw[t] >> 16;
                if (lo == gmin) {
                    unsigned long long k =
                        ((unsigned long long)__float_as_uint(frow[cbase]) << 32) | (unsigned)cbase;
                    best = k < best ? k : best;
                }
                if (hi == gmin) {
                    unsigned long long k =
                        ((unsigned long long)__float_as_uint(frow[cbase+1]) << 32) | (unsigned)(cbase+1);
                    best = k < best ? k : best;
                }
            }
            #pragma unroll
            for (int o = 16; o > 0; o >>= 1) {
                unsigned long long other = __shfl_down_sync(FULL, best, o);
                best = other < best ? other : best;
            }
            best = __shfl_sync(FULL, best, 0);
            idx = (int)(best & 0xffffffffu);
        }

        // update
        if (lane == 0) pred_b[step] = (float)idx;
        if (((idx >> 3) & 31) == lane) {
            int tt = (idx >> 8) * 4 + ((idx & 7) >> 1);
            unsigned int m = 0xFFFFu << (16 * (idx & 1));
            #pragma unroll
            for (int t = 0; t < 16; t++)
                if (t == tt) pat[t] |= m;
        }
        point = idx;
        rem--;
        step++;
    }

    const float padf = (float)pad;
    for (int s = step + lane; s < N; s += 32) pred_b[s] = padf;
}

// ============================================================================
// Fallback: proven 256-thread CTA-per-batch direct kernel (R4).
// ============================================================================
#define NTHREADS 256
#define NWARPS (NTHREADS / 32)

__global__ __launch_bounds__(NTHREADS, 1)
void greedy_nn_kernel(const float* __restrict__ distance,
                      const unsigned char* __restrict__ mraw,
                      const unsigned int* __restrict__ start_raw,
                      const unsigned int* __restrict__ pad_raw,
                      float* __restrict__ pred,
                      float* __restrict__ pred_len,
                      int N)
{
    __shared__ unsigned char s_msk[MSK_CAP];
    __shared__ unsigned long long s_partial[2][NWARPS];
    __shared__ int s_warpcnt[NWARPS];
    __shared__ int s_init[3];

    const int b    = blockIdx.x;
    const int tid  = threadIdx.x;
    const int lane = tid & 31;
    const int wid  = tid >> 5;

    const float* D = distance + (size_t)b * (size_t)N * (size_t)N;
    float* pred_b = pred + (size_t)b * N;
    const int pad = (pad_raw != nullptr) ? decode_scalar(*pad_raw, N) : N;

    if (tid == 0) {
        s_init[0] = (int)detect_word_mode(mraw);
        s_init[1] = decode_scalar(start_raw[b], N);
    }
    __syncthreads();
    const int word_mode = s_init[0];

    int cnt = 0;
    if (word_mode) {
        const unsigned int* m32 = (const unsigned int*)mraw + (size_t)b * N;
        for (int i = tid; i < N && i < MSK_CAP; i += NTHREADS) {
            unsigned char m = (m32[i] != 0u) ? 1 : 0;
            s_msk[i] = m; cnt += (m == 0);
        }
    } else {
        const unsigned char* m8 = mraw + (size_t)b * N;
        for (int i = tid; i < N && i < MSK_CAP; i += NTHREADS) {
            unsigned char m = m8[i] ? 1 : 0;
            s_msk[i] = m; cnt += (m == 0);
        }
    }
    for (int i = N + tid; i < MSK_CAP; i += NTHREADS) s_msk[i] = 1;

    #pragma unroll
    for (int o = 16; o > 0; o >>= 1) cnt += __shfl_down_sync(0xffffffffu, cnt, o);
    if (lane == 0) s_warpcnt[wid] = cnt;
    __syncthreads();
    if (tid == 0) {
        int r = 0;
        #pragma unroll
        for (int w = 0; w < NWARPS; w++) r += s_warpcnt[w];
        s_init[2] = r;
        pred_len[b] = (float)r;
    }
    __syncthreads();

    int rem   = s_init[2];
    int point = s_init[1];

    int step = 0;
    while (rem > 0) {
        const float* __restrict__ row = D + (size_t)point * N;
        const int p = step & 1;
        unsigned long long best = ~0ull;

        for (int base = tid * 4; base < N; base += NTHREADS * 4) {
            if (base + 3 < N) {
                float4 v = *reinterpret_cast<const float4*>(row + base);
                unsigned int mw = *reinterpret_cast<const unsigned int*>(s_msk + base);
                float v0 = (mw & 0x000000ffu) ? BIGF : v.x;
                float v1 = (mw & 0x0000ff00u) ? BIGF : v.y;
                float v2 = (mw & 0x00ff0000u) ? BIGF : v.z;
                float v3 = (mw & 0xff000000u) ? BIGF : v.w;
                unsigned long long k0 = ((unsigned long long)__float_as_uint(v0) << 32) | (unsigned)(base + 0);
                unsigned long long k1 = ((unsigned long long)__float_as_uint(v1) << 32) | (unsigned)(base + 1);
                unsigned long long k2 = ((unsigned long long)__float_as_uint(v2) << 32) | (unsigned)(base + 2);
                unsigned long long k3 = ((unsigned long long)__float_as_uint(v3) << 32) | (unsigned)(base + 3);
                unsigned long long ka = k0 < k1 ? k0 : k1;
                unsigned long long kb = k2 < k3 ? k2 : k3;
                unsigned long long kc = ka < kb ? ka : kb;
                best = kc < best ? kc : best;
            } else {
                for (int j = base; j < N; j++) {
                    float v = s_msk[j] ? BIGF : row[j];
                    unsigned long long k = ((unsigned long long)__float_as_uint(v) << 32) | (unsigned)j;
                    best = k < best ? k : best;
                }
            }
        }

        #pragma unroll
        for (int o = 16; o > 0; o >>= 1) {
            unsigned long long other = __shfl_down_sync(0xffffffffu, best, o);
            best = other < best ? other : best;
        }
        if (lane == 0) s_partial[p][wid] = best;
        __syncthreads();

        unsigned long long bb = s_partial[p][0];
        #pragma unroll
        for (int w = 1; w < NWARPS; w++) {
            unsigned long long q = s_partial[p][w];
            bb = q < bb ? q : bb;
        }
        int idx = (int)(bb & 0xffffffffu);
        s_msk[idx] = 1;
        point = idx;
        rem--;
        if (tid == 0) pred_b[step] = (float)idx;
        step++;
    }

    const float padf = (float)pad;
    for (int s = step + tid; s < N; s += NTHREADS) pred_b[s] = padf;
}

extern "C" void kernel_launch(void* const* d_in, const int* in_sizes, int n_in,
                              void* d_out, int out_size)
{
    // ---- identify inputs by size (order-independent) ----
    int di = 0;
    for (int i = 1; i < n_in; i++)
        if (in_sizes[i] > in_sizes[di]) di = i;              // distance (B*N*N)

    int mi = -1;
    for (int i = 0; i < n_in; i++) {
        if (i == di) continue;
        if (mi < 0 || in_sizes[i] > in_sizes[mi]) mi = i;    // mask (B*N)
    }

    const long long S_d = in_sizes[di];
    const long long S_m = in_sizes[mi];
    const int N = (int)(S_d / S_m);
    const int B = (int)(S_m / N);

    int si = -1, pi = -1;
    for (int i = 0; i < n_in; i++) {
        if (i == di || i == mi) continue;
        if (in_sizes[i] == B) si = i;
        else if (in_sizes[i] == 1) pi = i;
    }

    const float*         distance  = (const float*)d_in[di];
    const unsigned char* mask      = (const unsigned char*)d_in[mi];
    const unsigned int*  start_raw = (const unsigned int*)d_in[si];
    const unsigned int*  pad_raw   = (pi >= 0) ? (const unsigned int*)d_in[pi] : nullptr;

    float* pred     = (float*)d_out;          // (B, N) float32
    float* pred_len = pred + (size_t)B * N;   // (B,)

    const unsigned long long total = (unsigned long long)B * N * N;
    if (N <= 1024 && total <= SCRATCH_ELEMS) {
        compress_kernel<<<B * N, 128>>>(distance, mask, start_raw, N);
        greedy_key_kernel<<<B, 32>>>(distance, mask, start_raw, pad_raw,
                                     pred, pred_len, N);
    } else {
        greedy_nn_kernel<<<B, NTHREADS>>>(distance, mask, start_raw, pad_raw,
                                          pred, pred_len, N);
    }
}

// round 7
// speedup vs baseline: 1.5240x; 1.5240x over previous
#include <cuda_runtime.h>
#include <cuda_bf16.h>
#include <cstdint>

// Batched greedy nearest-neighbor selection, 2-kernel pipeline:
//   compress: needed rows -> u16 keys (top 16 float bits), padded to NK=1024
//             cols (0xFFFF fill). Distance reads = L2::evict_first, key writes
//             = L2::evict_last  => key working set (~66MB) stays L2-resident.
//   greedy:   1 warp/batch; per step one 2KB key row from L2; packed
//             (key16<<16|col) single-REDUX argmin; speculative next-row load
//             overlaps tie-detection; rare (≈0.8%/step) key ties resolved
//             exactly from fp32.
// Output (float32): pred (B,N) then pred_len (B,).

#define BIGF 1.0e6f
#define MSK_CAP 4096
#define NK 1024                                   // padded key-row stride (u16)
#define SCRATCH_ELEMS (68ull * 1024 * 1024)       // u16 elems (136MB)

__device__ unsigned short g_keys[SCRATCH_ELEMS];

__device__ __forceinline__ int decode_scalar(unsigned int w, int N)
{
    return (w <= (unsigned int)N) ? (int)w : (int)__uint_as_float(w);
}

__device__ __forceinline__ unsigned int detect_word_mode(const unsigned char* mraw)
{
    const unsigned int* mw = (const unsigned int*)mraw;
    bool all01 = true, allf = true;
    #pragma unroll 8
    for (int i = 0; i < 64; i++) {
        unsigned int w = mw[i];
        all01 &= (w == 0u || w == 1u);
        allf  &= (w == 0u || w == 0x3f800000u);
    }
    return (all01 || allf) ? 1u : 0u;
}

// ---- L2 cache policies ----
__device__ __forceinline__ unsigned long long pol_evict_first()
{
    unsigned long long p;
    asm("createpolicy.fractional.L2::evict_first.b64 %0, 1.0;" : "=l"(p));
    return p;
}
__device__ __forceinline__ unsigned long long pol_evict_last()
{
    unsigned long long p;
    asm("createpolicy.fractional.L2::evict_last.b64 %0, 1.0;" : "=l"(p));
    return p;
}
__device__ __forceinline__ float4 ldg_pol_f4(const float4* p, unsigned long long pol)
{
    float4 v;
    asm volatile("ld.global.nc.L2::cache_hint.v4.f32 {%0,%1,%2,%3}, [%4], %5;"
                 : "=f"(v.x), "=f"(v.y), "=f"(v.z), "=f"(v.w) : "l"(p), "l"(pol));
    return v;
}
__device__ __forceinline__ uint4 ldg_pol_u4(const uint4* p, unsigned long long pol)
{
    uint4 v;
    asm volatile("ld.global.nc.L2::cache_hint.v4.b32 {%0,%1,%2,%3}, [%4], %5;"
                 : "=r"(v.x), "=r"(v.y), "=r"(v.z), "=r"(v.w) : "l"(p), "l"(pol));
    return v;
}
__device__ __forceinline__ void stg_pol_u4(uint4* p, uint4 v, unsigned long long pol)
{
    asm volatile("st.global.L2::cache_hint.v4.b32 [%0], {%1,%2,%3,%4}, %5;"
                 :: "l"(p), "r"(v.x), "r"(v.y), "r"(v.z), "r"(v.w), "l"(pol) : "memory");
}

// ============================================================================
// Phase 1: one CTA per (b,row); 128 threads x 8 keys = 1024 (= NK).
// ============================================================================
__global__ __launch_bounds__(128, 8)
void compress_kernel(const float* __restrict__ distance,
                     const unsigned char* __restrict__ mraw,
                     const unsigned int* __restrict__ start_raw,
                     int N)
{
    const int r   = blockIdx.x;          // 0 .. B*N-1
    const int b   = r / N;
    const int row = r % N;
    const int tid = threadIdx.x;

    __shared__ int s_need;
    if (tid == 0) {
        unsigned int wm = detect_word_mode(mraw);
        int start = decode_scalar(start_raw[b], N);
        bool visited;
        if (wm) visited = ((const unsigned int*)mraw)[(size_t)b * N + row] != 0u;
        else    visited = mraw[(size_t)b * N + row] != 0;
        s_need = (!visited || row == start) ? 1 : 0;
    }
    __syncthreads();
    if (!s_need) return;

    const unsigned long long pf = pol_evict_first();
    const unsigned long long pl = pol_evict_last();

    const float* src = distance + (size_t)r * N;
    unsigned short* dst = g_keys + (size_t)r * NK;

    const int c = tid * 8;
    unsigned short k[8];
    if (c + 8 <= N) {
        float4 v0 = ldg_pol_f4((const float4*)(src + c), pf);
        float4 v1 = ldg_pol_f4((const float4*)(src + c + 4), pf);
        k[0] = (unsigned short)(__float_as_uint(v0.x) >> 16);
        k[1] = (unsigned short)(__float_as_uint(v0.y) >> 16);
        k[2] = (unsigned short)(__float_as_uint(v0.z) >> 16);
        k[3] = (unsigned short)(__float_as_uint(v0.w) >> 16);
        k[4] = (unsigned short)(__float_as_uint(v1.x) >> 16);
        k[5] = (unsigned short)(__float_as_uint(v1.y) >> 16);
        k[6] = (unsigned short)(__float_as_uint(v1.z) >> 16);
        k[7] = (unsigned short)(__float_as_uint(v1.w) >> 16);
    } else {
        #pragma unroll
        for (int p = 0; p < 8; p++)
            k[p] = (c + p < N) ? (unsigned short)(__float_as_uint(src[c + p]) >> 16)
                               : (unsigned short)0xFFFFu;
    }
    uint4 w;
    w.x = (unsigned int)k[0] | ((unsigned int)k[1] << 16);
    w.y = (unsigned int)k[2] | ((unsigned int)k[3] << 16);
    w.z = (unsigned int)k[4] | ((unsigned int)k[5] << 16);
    w.w = (unsigned int)k[6] | ((unsigned int)k[7] << 16);
    stg_pol_u4((uint4*)(dst + c), w, pl);
}

// ============================================================================
// Phase 2: one warp per batch. Lane owns cols j*256 + lane*8 + p (j<4,p<8);
// key word t=j*4+w holds cols (cl, cl+1), cl = (t>>2)*256 + lane*8 + ((t&3)<<1).
// ============================================================================
__device__ __forceinline__ void load_kw(unsigned int* kw, const unsigned short* krow,
                                        int lane, unsigned long long pol)
{
    #pragma unroll
    for (int j = 0; j < 4; j++) {
        uint4 v = ldg_pol_u4((const uint4*)(krow + j * 256 + lane * 8), pol);
        kw[j*4+0] = v.x; kw[j*4+1] = v.y; kw[j*4+2] = v.z; kw[j*4+3] = v.w;
    }
}

__global__ __launch_bounds__(32, 1)
void greedy_key_kernel(const float* __restrict__ distance,
                       const unsigned char* __restrict__ mraw,
                       const unsigned int* __restrict__ start_raw,
                       const unsigned int* __restrict__ pad_raw,
                       float* __restrict__ pred,
                       float* __restrict__ pred_len,
                       int N)
{
    const int lane = threadIdx.x;
    const int b    = blockIdx.x;
    const unsigned FULL = 0xffffffffu;
    const unsigned long long pl = pol_evict_last();

    const float* D = distance + (size_t)b * (size_t)N * (size_t)N;
    const unsigned short* KB = g_keys + (size_t)b * (size_t)N * NK;
    float* pred_b = pred + (size_t)b * N;

    unsigned int wm = 0; int point = 0, pad = N;
    if (lane == 0) {
        wm = detect_word_mode(mraw);
        point = decode_scalar(start_raw[b], N);
        if (pad_raw != nullptr) pad = decode_scalar(*pad_raw, N);
    }
    wm    = __shfl_sync(FULL, wm, 0);
    point = __shfl_sync(FULL, point, 0);
    pad   = __shfl_sync(FULL, pad, 0);

    // ---- col-pair constants, visited patterns, unvisited count ----
    const unsigned int* m32 = (const unsigned int*)mraw + (size_t)b * N;
    const unsigned char* m8 = mraw + (size_t)b * N;
    unsigned int pat[16], cv[16];
    int cnt = 0;
    #pragma unroll
    for (int t = 0; t < 16; t++) {
        int cl = ((t >> 2) << 8) + (lane << 3) + ((t & 3) << 1);
        cv[t] = (unsigned int)cl | ((unsigned int)(cl + 1) << 16);
        unsigned int pw = 0;
        #pragma unroll
        for (int p = 0; p < 2; p++) {
            int col = cl + p;
            bool v;
            if (col < N) v = wm ? (m32[col] != 0u) : (m8[col] != 0);
            else         v = true;
            if (v) pw |= 0xFFFFu << (16 * p);
            else   cnt++;
        }
        pat[t] = pw;
    }
    int rem = (int)__reduce_add_sync(FULL, (unsigned)cnt);
    if (lane == 0) pred_len[b] = (float)rem;

    unsigned int kw[16];
    load_kw(kw, KB + (size_t)point * NK, lane, pl);

    int step = 0;
    while (rem > 0) {
        // mask + pack (1 PRMT each) + min tree
        unsigned int packed[32];
        #pragma unroll
        for (int t = 0; t < 16; t++) {
            unsigned int kt = kw[t] | pat[t];
            packed[2*t]   = __byte_perm(kt, cv[t], 0x1054);  // {kt.b1,kt.b0,cv.b1,cv.b0}
            packed[2*t+1] = __byte_perm(kt, cv[t], 0x3276);  // {kt.b3,kt.b2,cv.b3,cv.b2}
        }
        #pragma unroll
        for (int s = 1; s < 32; s <<= 1) {
            #pragma unroll
            for (int i = 0; i + s < 32; i += 2 * s)
                packed[i] = packed[i] < packed[i+s] ? packed[i] : packed[i+s];
        }
        unsigned int gmin = __reduce_min_sync(FULL, packed[0]);
        int spec = (int)(gmin & 0xFFFFu);

        // speculative load of next row (overlaps tie detection + update)
        unsigned int kwn[16];
        load_kw(kwn, KB + (size_t)spec * NK, lane, pl);

        // tie detection: >=2 elements sharing the winning 16-bit key?
        const unsigned int wk = gmin >> 16;
        int mcnt = 0;
        #pragma unroll
        for (int t = 0; t < 16; t++) {
            unsigned int kt = kw[t] | pat[t];
            mcnt += ((kt & 0xFFFFu) == wk);
            mcnt += ((kt >> 16) == wk);
        }
        int total = (int)__reduce_add_sync(FULL, (unsigned)mcnt);

        int idx = spec;
        if (total >= 2) {
            // rare: duplicate min key -> exact fp32 resolution among matches
            const float* __restrict__ frow = D + (size_t)point * N;
            unsigned long long best = ~0ull;
            #pragma unroll
            for (int t = 0; t < 16; t++) {
                unsigned int kt = kw[t] | pat[t];
                int cl = (int)(cv[t] & 0xFFFFu);
                if ((kt & 0xFFFFu) == wk) {
                    unsigned long long kk =
                        ((unsigned long long)__float_as_uint(frow[cl]) << 32) | (unsigned)cl;
                    best = kk < best ? kk : best;
                }
                if ((kt >> 16) == wk) {
                    unsigned long long kk =
                        ((unsigned long long)__float_as_uint(frow[cl+1]) << 32) | (unsigned)(cl+1);
                    best = kk < best ? kk : best;
                }
            }
            #pragma unroll
            for (int o = 16; o > 0; o >>= 1) {
                unsigned long long other = __shfl_down_sync(FULL, best, o);
                best = other < best ? other : best;
            }
            best = __shfl_sync(FULL, best, 0);
            idx = (int)(best & 0xffffffffu);
            if (idx != spec)
                load_kw(kwn, KB + (size_t)idx * NK, lane, pl);   // respeculate (rare)
        }

        if (lane == 0) pred_b[step] = (float)idx;
        if (((idx >> 3) & 31) == lane) {
            const int tt = (idx >> 8) * 4 + ((idx & 7) >> 1);
            const unsigned int m = 0xFFFFu << (16 * (idx & 1));
            #pragma unroll
            for (int t = 0; t < 16; t++)
                if (t == tt) pat[t] |= m;
        }
        point = idx;
        rem--;
        step++;
        #pragma unroll
        for (int t = 0; t < 16; t++) kw[t] = kwn[t];
    }

    const float padf = (float)pad;
    for (int s = step + lane; s < N; s += 32) pred_b[s] = padf;
}

// ============================================================================
// Fallback: proven 256-thread CTA-per-batch direct kernel (R4).
// ============================================================================
#define NTHREADS 256
#define NWARPS (NTHREADS / 32)

__global__ __launch_bounds__(NTHREADS, 1)
void greedy_nn_kernel(const float* __restrict__ distance,
                      const unsigned char* __restrict__ mraw,
                      const unsigned int* __restrict__ start_raw,
                      const unsigned int* __restrict__ pad_raw,
                      float* __restrict__ pred,
                      float* __restrict__ pred_len,
                      int N)
{
    __shared__ unsigned char s_msk[MSK_CAP];
    __shared__ unsigned long long s_partial[2][NWARPS];
    __shared__ int s_warpcnt[NWARPS];
    __shared__ int s_init[3];

    const int b    = blockIdx.x;
    const int tid  = threadIdx.x;
    const int lane = tid & 31;
    const int wid  = tid >> 5;

    const float* D = distance + (size_t)b * (size_t)N * (size_t)N;
    float* pred_b = pred + (size_t)b * N;
    const int pad = (pad_raw != nullptr) ? decode_scalar(*pad_raw, N) : N;

    if (tid == 0) {
        s_init[0] = (int)detect_word_mode(mraw);
        s_init[1] = decode_scalar(start_raw[b], N);
    }
    __syncthreads();
    const int word_mode = s_init[0];

    int cnt = 0;
    if (word_mode) {
        const unsigned int* m32 = (const unsigned int*)mraw + (size_t)b * N;
        for (int i = tid; i < N && i < MSK_CAP; i += NTHREADS) {
            unsigned char m = (m32[i] != 0u) ? 1 : 0;
            s_msk[i] = m; cnt += (m == 0);
        }
    } else {
        const unsigned char* m8 = mraw + (size_t)b * N;
        for (int i = tid; i < N && i < MSK_CAP; i += NTHREADS) {
            unsigned char m = m8[i] ? 1 : 0;
            s_msk[i] = m; cnt += (m == 0);
        }
    }
    for (int i = N + tid; i < MSK_CAP; i += NTHREADS) s_msk[i] = 1;

    #pragma unroll
    for (int o = 16; o > 0; o >>= 1) cnt += __shfl_down_sync(0xffffffffu, cnt, o);
    if (lane == 0) s_warpcnt[wid] = cnt;
    __syncthreads();
    if (tid == 0) {
        int r = 0;
        #pragma unroll
        for (int w = 0; w < NWARPS; w++) r += s_warpcnt[w];
        s_init[2] = r;
        pred_len[b] = (float)r;
    }
    __syncthreads();

    int rem   = s_init[2];
    int point = s_init[1];

    int step = 0;
    while (rem > 0) {
        const float* __restrict__ row = D + (size_t)point * N;
        const int p = step & 1;
        unsigned long long best = ~0ull;

        for (int base = tid * 4; base < N; base += NTHREADS * 4) {
            if (base + 3 < N) {
                float4 v = *reinterpret_cast<const float4*>(row + base);
                unsigned int mw = *reinterpret_cast<const unsigned int*>(s_msk + base);
                float v0 = (mw & 0x000000ffu) ? BIGF : v.x;
                float v1 = (mw & 0x0000ff00u) ? BIGF : v.y;
                float v2 = (mw & 0x00ff0000u) ? BIGF : v.z;
                float v3 = (mw & 0xff000000u) ? BIGF : v.w;
                unsigned long long k0 = ((unsigned long long)__float_as_uint(v0) << 32) | (unsigned)(base + 0);
                unsigned long long k1 = ((unsigned long long)__float_as_uint(v1) << 32) | (unsigned)(base + 1);
                unsigned long long k2 = ((unsigned long long)__float_as_uint(v2) << 32) | (unsigned)(base + 2);
                unsigned long long k3 = ((unsigned long long)__float_as_uint(v3) << 32) | (unsigned)(base + 3);
                unsigned long long ka = k0 < k1 ? k0 : k1;
                unsigned long long kb = k2 < k3 ? k2 : k3;
                unsigned long long kc = ka < kb ? ka : kb;
                best = kc < best ? kc : best;
            } else {
                for (int j = base; j < N; j++) {
                    float v = s_msk[j] ? BIGF : row[j];
                    unsigned long long k = ((unsigned long long)__float_as_uint(v) << 32) | (unsigned)j;
                    best = k < best ? k : best;
                }
            }
        }

        #pragma unroll
        for (int o = 16; o > 0; o >>= 1) {
            unsigned long long other = __shfl_down_sync(0xffffffffu, best, o);
            best = other < best ? other : best;
        }
        if (lane == 0) s_partial[p][wid] = best;
        __syncthreads();

        unsigned long long bb = s_partial[p][0];
        #pragma unroll
        for (int w = 1; w < NWARPS; w++) {
            unsigned long long q = s_partial[p][w];
            bb = q < bb ? q : bb;
        }
        int idx = (int)(bb & 0xffffffffu);
        s_msk[idx] = 1;
        point = idx;
        rem--;
        if (tid == 0) pred_b[step] = (float)idx;
        step++;
    }

    const float padf = (float)pad;
    for (int s = step + tid; s < N; s += NTHREADS) pred_b[s] = padf;
}

extern "C" void kernel_launch(void* const* d_in, const int* in_sizes, int n_in,
                              void* d_out, int out_size)
{
    // ---- identify inputs by size (order-independent) ----
    int di = 0;
    for (int i = 1; i < n_in; i++)
        if (in_sizes[i] > in_sizes[di]) di = i;              // distance (B*N*N)

    int mi = -1;
    for (int i = 0; i < n_in; i++) {
        if (i == di) continue;
        if (mi < 0 || in_sizes[i] > in_sizes[mi]) mi = i;    // mask (B*N)
    }

    const long long S_d = in_sizes[di];
    const long long S_m = in_sizes[mi];
    const int N = (int)(S_d / S_m);
    const int B = (int)(S_m / N);

    int si = -1, pi = -1;
    for (int i = 0; i < n_in; i++) {
        if (i == di || i == mi) continue;
        if (in_sizes[i] == B) si = i;
        else if (in_sizes[i] == 1) pi = i;
    }

    const float*         distance  = (const float*)d_in[di];
    const unsigned char* mask      = (const unsigned char*)d_in[mi];
    const unsigned int*  start_raw = (const unsigned int*)d_in[si];
    const unsigned int*  pad_raw   = (pi >= 0) ? (const unsigned int*)d_in[pi] : nullptr;

    float* pred     = (float*)d_out;          // (B, N) float32
    float* pred_len = pred + (size_t)B * N;   // (B,)

    const unsigned long long key_elems = (unsigned long long)B * N * NK;
    if (N <= NK && key_elems <= SCRATCH_ELEMS) {
        compress_kernel<<<B * N, 128>>>(distance, mask, start_raw, N);
        greedy_key_kernel<<<B, 32>>>(distance, mask, start_raw, pad_raw,
                                     pred, pred_len, N);
    } else {
        greedy_nn_kernel<<<B, NTHREADS>>>(distance, mask, start_raw, pad_raw,
                                          pred, pred_len, N);
    }
}